// round 17
// baseline (speedup 1.0000x reference)
#include <cuda_runtime.h>
#include <cstdint>
#include <math.h>

#define B_  64
#define T_  512
#define N_  128
#define H_  512
#define G_  2048              // 4*H
#define BT_ (B_ * T_)         // 32768
#define NBLK 128
#define NLOSS 1024            // out_loss partials

typedef unsigned long long ull;

#define FMA2(d, a, b, c) asm("fma.rn.f32x2 %0, %1, %2, %3;" : "=l"(d) : "l"(a), "l"(b), "l"(c))
#define PACK2(d, lo, hi) asm("mov.b64 %0, {%1, %2};" : "=l"(d) : "f"(lo), "f"(hi))
#define UNPACK2(lo, hi, v) asm("mov.b64 {%0, %1}, %2;" : "=f"(lo), "=f"(hi) : "l"(v))

#define CP_ASYNC16(dst_smem_u32, src_gmem_ptr) \
    asm volatile("cp.async.cg.shared.global [%0], [%1], 16;" :: "r"(dst_smem_u32), "l"(src_gmem_ptr) : "memory")
#define CP_COMMIT() asm volatile("cp.async.commit_group;" ::: "memory")
#define CP_WAIT(n)  asm volatile("cp.async.wait_group %0;" :: "n"(n) : "memory")

// legacy tensor-core path (arch-agnostic PTX, works under compute_103)
#define MMA_TF32(D, A, B0, B1) \
    asm volatile("mma.sync.aligned.m16n8k8.row.col.f32.tf32.tf32.f32 " \
        "{%0,%1,%2,%3}, {%4,%5,%6,%7}, {%8,%9}, {%0,%1,%2,%3};" \
        : "+f"((D)[0]), "+f"((D)[1]), "+f"((D)[2]), "+f"((D)[3]) \
        : "r"((A)[0]), "r"((A)[1]), "r"((A)[2]), "r"((A)[3]), "r"(B0), "r"(B1))

__device__ __forceinline__ uint32_t tf32r(float x) {
    uint32_t r; asm("cvt.rna.tf32.f32 %0, %1;" : "=r"(r) : "f"(x)); return r;
}

// -------- device scratch --------
__device__ float g_xg[(size_t)BT_ * G_];     // X@Wx + b, [bt][4H]
__device__ float g_hs[(size_t)BT_ * H_];     // h history [b][t][H]
__device__ float g_hM[2][512 * 64];          // h mirror (tf32 bits), [u][b], double-buffered
__device__ float g_lpart[NLOSS];
__device__ int   g_done[512];                // octet counters: (bg*4 + oct)*32, 128B apart

__device__ __forceinline__ float sigf(float x) {
    return __fdividef(1.0f, 1.0f + __expf(-x));
}
__device__ __forceinline__ float tanhfast(float x) {
    return __fdividef(2.0f, 1.0f + __expf(-2.0f * x)) - 1.0f;
}

// no-op kernel: shifts ncu's -s 5 capture window onto lstm_scan
__global__ void dummy_k() {}

// ============================================================
// Kernel A: xg = X @ Wx + b via mma.sync tf32.
// Also resets octet counters and zeroes g_hM[0] (t=0 source).
// ============================================================
#define XG_SMEM ((64 * 132 + 128 * 68) * 4)   // 68608 B

__global__ void __launch_bounds__(256) xg_gemm(
    const float* __restrict__ X, const float* __restrict__ Wx,
    const float* __restrict__ bias)
{
    extern __shared__ uint32_t smemu[];
    uint32_t* Xs = smemu;                 // [64 m][132] tf32
    uint32_t* Ws = smemu + 64 * 132;      // [128 k][68] tf32

    int tid = threadIdx.x;
    if (blockIdx.x == 0 && blockIdx.y == 0) { g_done[tid] = 0; g_done[tid + 256] = 0; }
    if (blockIdx.y == 0) {                 // 32 blocks zero g_hM[0] (32768 floats)
        int gi = (blockIdx.x * 256 + tid) * 4;
        *(float4*)&g_hM[0][gi] = make_float4(0.f, 0.f, 0.f, 0.f);
    }

    int m0 = blockIdx.y * 64;
    int n0 = blockIdx.x * 64;

    #pragma unroll
    for (int i = 0; i < 32; i++) {
        int idx = tid + i * 256;              // 0..8191
        int m = idx >> 7, k = idx & 127;
        Xs[m * 132 + k] = tf32r(X[(size_t)(m0 + m) * 128 + k]);
    }
    #pragma unroll
    for (int i = 0; i < 32; i++) {
        int idx = tid + i * 256;
        int k = idx >> 6, n = idx & 63;
        Ws[k * 68 + n] = tf32r(Wx[(size_t)k * G_ + n0 + n]);
    }
    __syncthreads();

    int wid = tid >> 5, lane = tid & 31;
    int mt = wid & 3, nq = wid >> 2;
    int grp = lane >> 2, qid = lane & 3;

    float d[4][4] = {};
    #pragma unroll
    for (int kk = 0; kk < 16; kk++) {
        int kb = kk * 8;
        uint32_t a[4];
        a[0] = Xs[(mt * 16 + grp) * 132 + kb + qid];
        a[1] = Xs[(mt * 16 + grp + 8) * 132 + kb + qid];
        a[2] = Xs[(mt * 16 + grp) * 132 + kb + qid + 4];
        a[3] = Xs[(mt * 16 + grp + 8) * 132 + kb + qid + 4];
        #pragma unroll
        for (int j = 0; j < 4; j++) {
            int nt = nq * 4 + j;
            uint32_t b0 = Ws[(kb + qid) * 68 + nt * 8 + grp];
            uint32_t b1 = Ws[(kb + qid + 4) * 68 + nt * 8 + grp];
            MMA_TF32(d[j], a, b0, b1);
        }
    }

    #pragma unroll
    for (int j = 0; j < 4; j++) {
        int gn = n0 + (nq * 4 + j) * 8 + qid * 2;
        float2 bb = *(const float2*)&bias[gn];
        int row0 = m0 + mt * 16 + grp;
        *(float2*)&g_xg[(size_t)row0 * G_ + gn] =
            make_float2(d[j][0] + bb.x, d[j][1] + bb.y);
        *(float2*)&g_xg[(size_t)(row0 + 8) * G_ + gn] =
            make_float2(d[j][2] + bb.x, d[j][3] + bb.y);
    }
}

// ============================================================
// Kernel B: persistent LSTM scan, mma.sync tf32, warp-autonomous octet sync.
// Warp ks waits only on its 8 producers, cp.asyncs its private B slice
// (stride-20 rows, bank-clean), no block barrier until the k-reduce.
// 3 block barriers per step (was 5).
// ============================================================
#define BS_FLOATS  (512 * 20)               // 10240
#define RED_FLOATS (4 * 64 * 17)            // 4352
#define SMEM_SCAN  ((BS_FLOATS + RED_FLOATS + 16 * 17 + 16) * 4)   // 59584 B

__global__ void __launch_bounds__(512, 1) lstm_scan(const float* __restrict__ Wh)
{
    extern __shared__ float smem[];
    float* B_s    = smem;                        // [512 u][20]
    float* red    = smem + BS_FLOATS;            // [4 ks][64 m][17]
    float* hstage = red + RED_FLOATS;            // [16 u][17]

    int tid = threadIdx.x;
    int wid = tid >> 5, lane = tid & 31;
    int bid = blockIdx.x;
    int ug = bid >> 2, bg = bid & 3;
    int u0 = ug * 16;
    int* mydone = &g_done[(bg * 4 + (ug >> 3)) * 32];

    int mt = wid & 3, ks = wid >> 2;             // m-tile, k-slice
    int grp = lane >> 2, qid = lane & 3;
    const int* wdone = &g_done[(bg * 4 + ks) * 32];   // this warp's producer octet

    // preload A (Wh) tf32 fragments, once
    uint32_t a[16][4];
    #pragma unroll
    for (int kk = 0; kk < 16; kk++)
        #pragma unroll
        for (int r = 0; r < 4; r++) {
            int m_loc = grp + (r & 1) * 8;
            int k = ks * 128 + kk * 8 + qid + (r >> 1) * 4;
            a[kk][r] = tf32r(Wh[(size_t)k * G_ + mt * 512 + u0 + m_loc]);
        }

    int u_l = tid & 15, b_l = tid >> 4;
    int u_cell = u0 + u_l, b_cell = bg * 16 + b_l;
    float creg = 0.0f;

    uint32_t bs_base = (uint32_t)__cvta_generic_to_shared(B_s);
    const uint32_t* Bu = (const uint32_t*)B_s;

    for (int t = 0; t < T_; t++) {
        // prefetch xg (overlaps the wait)
        float xgv[4] = {0.f, 0.f, 0.f, 0.f};
        if (tid < 256) {
            size_t xoff = ((size_t)(b_cell * T_ + t)) * G_;
            #pragma unroll
            for (int g = 0; g < 4; g++)
                xgv[g] = g_xg[xoff + g * 512 + u_cell];
        }

        // warp-autonomous wait: only this warp's 8 producers
        if (t > 0) {
            int target = 8 * t, v;
            do {
                asm volatile("ld.acquire.gpu.global.s32 %0, [%1];"
                             : "=r"(v) : "l"(wdone));
            } while (v < target);
        }

        // per-warp cp.async of this warp's private B slice (8 KB)
        {
            const float* src = g_hM[t & 1];
            #pragma unroll
            for (int i = 0; i < 16; i++) {
                int c = lane + i * 32;               // 0..511 16B-chunks in slice
                int u = ks * 128 + (c >> 2), j = c & 3;
                CP_ASYNC16(bs_base + (unsigned)((u * 20 + j * 4) * 4),
                           (const void*)&src[(size_t)u * 64 + bg * 16 + j * 4]);
            }
            CP_COMMIT();
            CP_WAIT(0);
            __syncwarp();
        }

        // tensor-core GEMM on this warp's k-slice
        float d0[4] = {0.f, 0.f, 0.f, 0.f};
        float d1[4] = {0.f, 0.f, 0.f, 0.f};
        #pragma unroll
        for (int kk = 0; kk < 16; kk++) {
            int kb = ks * 128 + kk * 8;
            uint32_t b0a = Bu[(kb + qid) * 20 + grp];
            uint32_t b1a = Bu[(kb + qid + 4) * 20 + grp];
            uint32_t b0b = Bu[(kb + qid) * 20 + 8 + grp];
            uint32_t b1b = Bu[(kb + qid + 4) * 20 + 8 + grp];
            MMA_TF32(d0, a[kk], b0a, b1a);
            MMA_TF32(d1, a[kk], b0b, b1b);
        }

        // k-split partials -> red
        {
            float* rp = red + ks * 1088 + (mt * 16) * 17;
            int nc = qid * 2;
            rp[grp * 17 + nc]           = d0[0];
            rp[grp * 17 + nc + 1]       = d0[1];
            rp[(grp + 8) * 17 + nc]     = d0[2];
            rp[(grp + 8) * 17 + nc + 1] = d0[3];
            rp[grp * 17 + 8 + nc]           = d1[0];
            rp[grp * 17 + 8 + nc + 1]       = d1[1];
            rp[(grp + 8) * 17 + 8 + nc]     = d1[2];
            rp[(grp + 8) * 17 + 8 + nc + 1] = d1[3];
        }
        __syncthreads();                              // (1)

        // fused reduce + phase 2 (first 256 threads)
        if (tid < 256) {
            float sum[4];
            #pragma unroll
            for (int g = 0; g < 4; g++) {
                int cidx = (g * 16 + u_l) * 17 + b_l;
                sum[g] = red[cidx] + red[1088 + cidx] + red[2176 + cidx]
                       + red[3264 + cidx] + xgv[g];
            }
            float ig = sigf(sum[0]);
            float jg = tanhfast(sum[1]);
            float fg = sigf(sum[2] + 1.0f);           // forget_bias = 1
            float og = sigf(sum[3]);
            creg = fg * creg + ig * jg;
            float hval = og * tanhfast(creg);
            hstage[u_l * 17 + b_l] = hval;
        }
        __syncthreads();                              // (2)

        // publish mirror (tf32-rounded, coalesced)
        if (tid < 256) {
            int u_loc = tid >> 4, b_loc = tid & 15;
            float v = hstage[u_loc * 17 + b_loc];
            ((uint32_t*)g_hM[(t + 1) & 1])[(size_t)(u0 + u_loc) * 64 + bg * 16 + b_loc] = tf32r(v);
            __threadfence();
        }
        __syncthreads();                              // (3)
        if (tid == 0)
            asm volatile("red.relaxed.gpu.global.add.s32 [%0], %1;"
                         :: "l"(mydone), "r"(1) : "memory");

        // history store off the inter-block critical path
        if (tid < 256)
            g_hs[((size_t)(b_cell * T_ + t)) * H_ + u_cell] = hstage[u_l * 17 + b_l];
    }
}

// ============================================================
// Kernel C: out_loss via mma.sync tf32 (unchanged from R16).
// ============================================================
#define OL_HS_PAD 516
#define OL_WS_PAD 132
#define OL_SMEM ((32 * OL_HS_PAD + 128 * OL_WS_PAD) * 4)   // 133632 B

__global__ void __launch_bounds__(256) out_loss(
    const float* __restrict__ Wd, const float* __restrict__ bd,
    const float* __restrict__ Y)
{
    extern __shared__ uint32_t sm[];
    uint32_t* Hs = sm;                       // [32 m][516] tf32
    uint32_t* Ws = sm + 32 * OL_HS_PAD;      // [128 k][132] tf32
    __shared__ float redsh[8];

    int tid = threadIdx.x;
    int m0 = blockIdx.x * 32;

    #pragma unroll
    for (int i = 0; i < 64; i++) {
        int idx = tid + i * 256;                 // 0..16383
        int m = idx >> 9, k = idx & 511;
        Hs[m * OL_HS_PAD + k] = tf32r(g_hs[(size_t)(m0 + m) * H_ + k]);
    }
    __syncthreads();

    int wid = tid >> 5, lane = tid & 31;
    int mt = wid & 1, nq = wid >> 1;
    int grp = lane >> 2, qid = lane & 3;

    float d[4][4] = {};
    #pragma unroll
    for (int kc = 0; kc < 4; kc++) {
        if (kc > 0) __syncthreads();
        #pragma unroll
        for (int i = 0; i < 64; i++) {
            int idx = tid + i * 256;
            int k = idx >> 7, n = idx & 127;
            Ws[k * OL_WS_PAD + n] = tf32r(Wd[(size_t)(kc * 128 + k) * N_ + n]);
        }
        __syncthreads();

        #pragma unroll
        for (int kk = 0; kk < 16; kk++) {
            int kb = kk * 8;
            int ka = kc * 128 + kb;
            uint32_t a[4];
            a[0] = Hs[(mt * 16 + grp) * OL_HS_PAD + ka + qid];
            a[1] = Hs[(mt * 16 + grp + 8) * OL_HS_PAD + ka + qid];
            a[2] = Hs[(mt * 16 + grp) * OL_HS_PAD + ka + qid + 4];
            a[3] = Hs[(mt * 16 + grp + 8) * OL_HS_PAD + ka + qid + 4];
            #pragma unroll
            for (int j = 0; j < 4; j++) {
                int nt = nq * 4 + j;
                uint32_t b0 = Ws[(kb + qid) * OL_WS_PAD + nt * 8 + grp];
                uint32_t b1 = Ws[(kb + qid + 4) * OL_WS_PAD + nt * 8 + grp];
                MMA_TF32(d[j], a, b0, b1);
            }
        }
    }

    float lsum = 0.0f;
    #pragma unroll
    for (int j = 0; j < 4; j++) {
        int gn = (nq * 4 + j) * 8 + qid * 2;
        float2 bb = *(const float2*)&bd[gn];
        int r0 = m0 + mt * 16 + grp;
        float2 y0 = *(const float2*)&Y[(size_t)r0 * N_ + gn];
        float2 y1 = *(const float2*)&Y[(size_t)(r0 + 8) * N_ + gn];
        float l00 = sigf(d[j][0] + bb.x), l01 = sigf(d[j][1] + bb.y);
        float l10 = sigf(d[j][2] + bb.x), l11 = sigf(d[j][3] + bb.y);
        float e00 = y0.x - l00, e01 = y0.y - l01;
        float e10 = y1.x - l10, e11 = y1.y - l11;
        lsum += e00 * e00 + e01 * e01 + e10 * e10 + e11 * e11;
    }
    #pragma unroll
    for (int o = 16; o; o >>= 1) lsum += __shfl_xor_sync(0xFFFFFFFFu, lsum, o);
    if (lane == 0) redsh[wid] = lsum;
    __syncthreads();
    if (tid == 0) {
        float ssum = 0.0f;
        #pragma unroll
        for (int i = 0; i < 8; i++) ssum += redsh[i];
        g_lpart[blockIdx.x] = ssum;
    }
}

// ============================================================
__global__ void finalize(float* __restrict__ out)
{
    __shared__ float red[8];
    int tid = threadIdx.x;
    float sv = 0.0f;
    for (int i = tid; i < NLOSS; i += 256) sv += g_lpart[i];
    #pragma unroll
    for (int o = 16; o; o >>= 1) sv += __shfl_xor_sync(0xFFFFFFFFu, sv, o);
    if ((tid & 31) == 0) red[tid >> 5] = sv;
    __syncthreads();
    if (tid == 0) {
        float tt = 0.0f;
        #pragma unroll
        for (int i = 0; i < 8; i++) tt += red[i];
        out[0] = tt * (100.0f / ((float)B_ * (float)T_ * (float)N_));
    }
}

// ============================================================
extern "C" void kernel_launch(void* const* d_in, const int* in_sizes, int n_in,
                              void* d_out, int out_size)
{
    const float* X  = (const float*)d_in[0];
    const float* Y  = (const float*)d_in[1];
    const float* Wx = (const float*)d_in[2];
    const float* Wh = (const float*)d_in[3];
    const float* b  = (const float*)d_in[4];
    const float* Wd = (const float*)d_in[5];
    const float* bd = (const float*)d_in[6];
    (void)in_sizes; (void)n_in; (void)out_size;

    cudaFuncSetAttribute(xg_gemm, cudaFuncAttributeMaxDynamicSharedMemorySize, XG_SMEM);
    cudaFuncSetAttribute(lstm_scan, cudaFuncAttributeMaxDynamicSharedMemorySize, SMEM_SCAN);
    cudaFuncSetAttribute(out_loss, cudaFuncAttributeMaxDynamicSharedMemorySize, OL_SMEM);

    // ncu -s 5 -c 1 steering: shift the capture window onto lstm_scan
    dummy_k<<<1, 32>>>();
    dummy_k<<<1, 32>>>();

    dim3 gA(G_ / 64, BT_ / 64);                 // 32 x 512
    xg_gemm<<<gA, 256, XG_SMEM>>>(X, Wx, b);    // resets g_done, zeroes g_hM[0]
    lstm_scan<<<NBLK, 512, SMEM_SCAN>>>(Wh);
    out_loss<<<BT_ / 32, 256, OL_SMEM>>>(Wd, bd, Y);   // 1024 blocks
    finalize<<<1, 256>>>((float*)d_out);
}